// round 3
// baseline (speedup 1.0000x reference)
#include <cuda_runtime.h>
#include <cstdint>

// Deformable conv2d: B=2, CIN=64, H=128, W=256, COUT=64, K=3, s=1, p=1, d=1
#define B_N   2
#define C_IN  64
#define H_IN  128
#define W_IN  256
#define C_OUT 64
#define KK    9
#define H_O   128
#define W_O   256
#define HW    (H_IN * W_IN)     // 32768
#define HWO   (H_O * W_O)       // 32768
#define NPIX  (B_N * HWO)       // 65536

#define TPX   128               // pixels per block
#define TPB   256
#define DS    132               // duplicated-S row stride in floats (128 + 4 pad)

// dynamic smem layout (floats):
//   S   : TPX * DS   (samples duplicated: [px][2*cin] == [px][2*cin+1])
//   Wsh : 64 * 64
//   Pi  : 4 * TPX (ints)
//   Pa  : 4 * TPX
#define SMEM_FLOATS (TPX * DS + 4096 + 4 * TPX + 4 * TPX)
#define SMEM_BYTES  (SMEM_FLOATS * 4)

typedef unsigned long long u64;

__device__ float g_xt[(size_t)B_N * HW * C_IN];   // NHWC scratch, 16 MB
__device__ float g_wt[KK * C_IN * C_OUT];         // [k][cin][cout], 144 KB

__device__ __forceinline__ u64 pack2(float lo, float hi) {
    u64 r;
    asm("mov.b64 %0, {%1, %2};" : "=l"(r) : "f"(lo), "f"(hi));
    return r;
}
__device__ __forceinline__ void unpack2(u64 v, float& lo, float& hi) {
    asm("mov.b64 {%0, %1}, %2;" : "=f"(lo), "=f"(hi) : "l"(v));
}
__device__ __forceinline__ u64 fma2(u64 a, u64 b, u64 c) {
    u64 d;
    asm("fma.rn.f32x2 %0, %1, %2, %3;" : "=l"(d) : "l"(a), "l"(b), "l"(c));
    return d;
}

// ---- NCHW -> NHWC transpose ----
__global__ void transpose_nchw_nhwc(const float* __restrict__ x) {
    __shared__ float tile[32][33];
    const int b   = blockIdx.z;
    const int c0  = blockIdx.y * 32;
    const int hw0 = blockIdx.x * 32;
    const int tx  = threadIdx.x;
    const int ty  = threadIdx.y;   // block (32, 8)
    const float* xb = x + (size_t)b * C_IN * HW;
    float* xtb = g_xt + (size_t)b * HW * C_IN;
#pragma unroll
    for (int j = 0; j < 32; j += 8)
        tile[ty + j][tx] = xb[(size_t)(c0 + ty + j) * HW + hw0 + tx];
    __syncthreads();
#pragma unroll
    for (int j = 0; j < 32; j += 8)
        xtb[(size_t)(hw0 + ty + j) * C_IN + c0 + tx] = tile[tx][ty + j];
}

// ---- weight [cout][cin][k] -> [k][cin][cout] ----
__global__ void transpose_weight(const float* __restrict__ weight) {
    int i = blockIdx.x * 256 + threadIdx.x;
    if (i < KK * C_IN * C_OUT) {
        int k    = i / (C_IN * C_OUT);
        int r    = i - k * (C_IN * C_OUT);
        int cin  = r >> 6;
        int cout = r & 63;
        g_wt[i] = weight[(cout * C_IN + cin) * KK + k];
    }
}

// ---- main kernel ----
__global__ __launch_bounds__(TPB, 2)
void deform_main(const float* __restrict__ offset,
                 const float* __restrict__ bias,
                 float* __restrict__ out) {
    extern __shared__ float sm[];
    float* S   = sm;                              // [TPX][DS], duplicated pairs
    float* Wsh = sm + TPX * DS;                   // [64 cin][64 cout]
    int*   Pi  = (int*)(Wsh + 4096);              // [4][TPX]
    float* Pa  = (float*)(Pi + 4 * TPX);          // [4][TPX]

    const int tid = threadIdx.x;
    const int p0  = blockIdx.x * TPX;
    const int b   = p0 >> 15;
    const int rem = p0 & (HWO - 1);
    const int ho  = rem >> 8;
    const int wo0 = rem & (W_O - 1);

    const int coutg = tid & 15;         // 16 groups of 4 couts
    const int pxg   = tid >> 4;         // 16 groups of 8 px
    const int c0    = coutg * 4;
    const int px0   = pxg * 8;

    // acc[cp][j]: f32x2 lanes = couts (c0+2cp, c0+2cp+1), pixel px0+j
    u64 acc[2][8];
    {
        const float b0 = __ldg(bias + c0 + 0);
        const float b1 = __ldg(bias + c0 + 1);
        const float b2 = __ldg(bias + c0 + 2);
        const float b3 = __ldg(bias + c0 + 3);
        const u64 p01 = pack2(b0, b1);
        const u64 p23 = pack2(b2, b3);
#pragma unroll
        for (int j = 0; j < 8; j++) { acc[0][j] = p01; acc[1][j] = p23; }
    }

    const float* offb = offset + (size_t)b * 2 * KK * HWO + ho * W_O + wo0;
    const float* xtb  = g_xt + (size_t)b * HW * C_IN;

    for (int k = 0; k < KK; k++) {
        __syncthreads();   // previous iteration's S/Wsh readers done

        // stage this k's weight tile (coalesced float4 copy)
        {
            const float4* src = (const float4*)(g_wt + k * (C_IN * C_OUT));
            float4* dst = (float4*)Wsh;
#pragma unroll
            for (int i = tid; i < 1024; i += TPB) dst[i] = src[i];
        }

        // per-pixel bilinear params -> smem (threads 0..127)
        if (tid < TPX) {
            const float offy = __ldg(offb + (2 * k + 0) * HWO + tid);
            const float offx = __ldg(offb + (2 * k + 1) * HWO + tid);
            const float py = (float)(ho - 1 + k / 3) + offy;
            const float px = (float)(wo0 + tid - 1 + k % 3) + offx;
            const float y0f = floorf(py);
            const float x0f = floorf(px);
            const int   y0  = (int)y0f;
            const int   x0  = (int)x0f;
            const float wy  = py - y0f;
            const float wx  = px - x0f;
            const int   y1  = y0 + 1;
            const int   x1  = x0 + 1;
            const bool vy0 = (y0 >= 0) && (y0 < H_IN);
            const bool vy1 = (y1 >= 0) && (y1 < H_IN);
            const bool vx0 = (x0 >= 0) && (x0 < W_IN);
            const bool vx1 = (x1 >= 0) && (x1 < W_IN);
            const int cy0 = min(max(y0, 0), H_IN - 1);
            const int cy1 = min(max(y1, 0), H_IN - 1);
            const int cx0 = min(max(x0, 0), W_IN - 1);
            const int cx1 = min(max(x1, 0), W_IN - 1);
            Pi[0 * TPX + tid] = cy0 * W_IN + cx0;
            Pi[1 * TPX + tid] = cy0 * W_IN + cx1;
            Pi[2 * TPX + tid] = cy1 * W_IN + cx0;
            Pi[3 * TPX + tid] = cy1 * W_IN + cx1;
            Pa[0 * TPX + tid] = (vy0 && vx0) ? (1.0f - wy) * (1.0f - wx) : 0.0f;
            Pa[1 * TPX + tid] = (vy0 && vx1) ? (1.0f - wy) * wx          : 0.0f;
            Pa[2 * TPX + tid] = (vy1 && vx0) ? wy * (1.0f - wx)          : 0.0f;
            Pa[3 * TPX + tid] = (vy1 && vx1) ? wy * wx                   : 0.0f;
        }
        __syncthreads();

        // fill S[px][2*cin] duplicated. lane mapping: 16 consecutive lanes
        // cover one pixel's 64 channels -> coalesced LDG.128 from NHWC x.
#pragma unroll
        for (int i = 0; i < 8; i++) {
            const int u  = tid + TPB * i;
            const int cg = u & 15;       // channel group (4 channels)
            const int px = u >> 4;       // pixel in tile
            const int i00 = Pi[0 * TPX + px];
            const int i01 = Pi[1 * TPX + px];
            const int i10 = Pi[2 * TPX + px];
            const int i11 = Pi[3 * TPX + px];
            const float a00 = Pa[0 * TPX + px];
            const float a01 = Pa[1 * TPX + px];
            const float a10 = Pa[2 * TPX + px];
            const float a11 = Pa[3 * TPX + px];
            const float4 v00 = __ldg((const float4*)(xtb + (size_t)i00 * C_IN) + cg);
            const float4 v01 = __ldg((const float4*)(xtb + (size_t)i01 * C_IN) + cg);
            const float4 v10 = __ldg((const float4*)(xtb + (size_t)i10 * C_IN) + cg);
            const float4 v11 = __ldg((const float4*)(xtb + (size_t)i11 * C_IN) + cg);
            float4 r;
            r.x = fmaf(v00.x, a00, fmaf(v01.x, a01, fmaf(v10.x, a10, v11.x * a11)));
            r.y = fmaf(v00.y, a00, fmaf(v01.y, a01, fmaf(v10.y, a10, v11.y * a11)));
            r.z = fmaf(v00.z, a00, fmaf(v01.z, a01, fmaf(v10.z, a10, v11.z * a11)));
            r.w = fmaf(v00.w, a00, fmaf(v01.w, a10 * 0.0f + a01, fmaf(v10.w, a10, v11.w * a11))); // placeholder removed below
            r.w = fmaf(v00.w, a00, fmaf(v01.w, a01, fmaf(v10.w, a10, v11.w * a11)));
            // duplicated store: two STS.128, conflict-free (DS=132 keeps 16B align)
            float* dst = S + px * DS + 8 * cg;
            *(float4*)(dst + 0) = make_float4(r.x, r.x, r.y, r.y);
            *(float4*)(dst + 4) = make_float4(r.z, r.z, r.w, r.w);
        }
        __syncthreads();

        // GEMM: acc[cout 4][px 8] += W[cin][cout] * S[px][cin]
        // per cin: 1 LDS.128 (weights) + 8 LDS.64 (dup samples) + 16 FFMA2
#pragma unroll 4
        for (int cin = 0; cin < C_IN; cin++) {
            const ulonglong2 wv = *(const ulonglong2*)(Wsh + cin * C_OUT + c0); // LDS.128
            const float* srow = S + px0 * DS + 2 * cin;
#pragma unroll
            for (int j = 0; j < 8; j++) {
                const u64 s2 = *(const u64*)(srow + j * DS);   // LDS.64 (s,s)
                acc[0][j] = fma2(wv.x, s2, acc[0][j]);
                acc[1][j] = fma2(wv.y, s2, acc[1][j]);
            }
        }
    }

    // epilogue: out[b][cout][ho][wo], float4 along px
    float* ob = out + (size_t)b * C_OUT * HWO + ho * W_O + wo0 + px0;
#pragma unroll
    for (int cp = 0; cp < 2; cp++) {
        float lo[8], hi[8];
#pragma unroll
        for (int j = 0; j < 8; j++) unpack2(acc[cp][j], lo[j], hi[j]);
        float* r0 = ob + (size_t)(c0 + 2 * cp + 0) * HWO;
        float* r1 = ob + (size_t)(c0 + 2 * cp + 1) * HWO;
        ((float4*)r0)[0] = make_float4(lo[0], lo[1], lo[2], lo[3]);
        ((float4*)r0)[1] = make_float4(lo[4], lo[5], lo[6], lo[7]);
        ((float4*)r1)[0] = make_float4(hi[0], hi[1], hi[2], hi[3]);
        ((float4*)r1)[1] = make_float4(hi[4], hi[5], hi[6], hi[7]);
    }
}

extern "C" void kernel_launch(void* const* d_in, const int* in_sizes, int n_in,
                              void* d_out, int out_size) {
    const float* x      = (const float*)d_in[0];
    const float* offset = (const float*)d_in[1];
    const float* weight = (const float*)d_in[2];
    const float* bias   = (const float*)d_in[3];
    float* out = (float*)d_out;
    (void)in_sizes; (void)n_in; (void)out_size;

    cudaFuncSetAttribute(deform_main,
                         cudaFuncAttributeMaxDynamicSharedMemorySize, SMEM_BYTES);

    dim3 tg(HW / 32, C_IN / 32, B_N);
    transpose_nchw_nhwc<<<tg, dim3(32, 8)>>>(x);
    transpose_weight<<<(KK * C_IN * C_OUT + 255) / 256, 256>>>(weight);
    deform_main<<<NPIX / TPX, TPB, SMEM_BYTES>>>(offset, bias, out);
}

// round 5
// speedup vs baseline: 1.4348x; 1.4348x over previous
#include <cuda_runtime.h>
#include <cuda_bf16.h>
#include <mma.h>
#include <cstdint>

using namespace nvcuda;

// Deformable conv2d: B=2, CIN=64, H=128, W=256, COUT=64, K=3, s=1, p=1, d=1
#define B_N   2
#define C_IN  64
#define H_IN  128
#define W_IN  256
#define C_OUT 64
#define NTAP  9
#define H_O   128
#define W_O   256
#define HW    (H_IN * W_IN)     // 32768
#define HWO   (H_O * W_O)       // 32768
#define NPIX  (B_N * HWO)       // 65536

#define TPX   128               // pixels (M) per CTA tile
#define TPB   256               // 8 warps

#define ALD   72                // A smem leading dim (bf16 elems), mult of 8
#define WLD   72                // W smem leading dim
#define OLD   68                // epilogue f32 leading dim, mult of 4

// dynamic smem layout (bytes):
#define AH_OFF 0
#define AL_OFF 18432            // 128*72*2
#define WH_OFF 36864
#define WL_OFF 46080            // + 64*72*2
#define SMEM_BYTES 55296        // + 64*72*2
// epilogue reuses [0, 128*68*4) = 34816 bytes as float Osm

__device__ float g_xt[(size_t)B_N * HW * C_IN];          // NHWC fp32, 16 MB
__device__ __nv_bfloat16 g_wh[NTAP * C_IN * WLD];        // [k][cin][cout] hi
__device__ __nv_bfloat16 g_wl[NTAP * C_IN * WLD];        // lo

// ---- NCHW -> NHWC fp32 transpose ----
__global__ void transpose_nchw_nhwc(const float* __restrict__ x) {
    __shared__ float tile[32][33];
    const int b   = blockIdx.z;
    const int c0  = blockIdx.y * 32;
    const int hw0 = blockIdx.x * 32;
    const int tx  = threadIdx.x;
    const int ty  = threadIdx.y;   // block (32, 8)
    const float* xb = x + (size_t)b * C_IN * HW;
    float* xtb = g_xt + (size_t)b * HW * C_IN;
#pragma unroll
    for (int j = 0; j < 32; j += 8)
        tile[ty + j][tx] = xb[(size_t)(c0 + ty + j) * HW + hw0 + tx];
    __syncthreads();
#pragma unroll
    for (int j = 0; j < 32; j += 8)
        xtb[(size_t)(hw0 + ty + j) * C_IN + c0 + tx] = tile[tx][ty + j];
}

// ---- weight [cout][cin][k] -> bf16 hi/lo [k][cin][cout(+pad)] ----
__global__ void prep_weights(const float* __restrict__ w) {
    int i = blockIdx.x * 256 + threadIdx.x;
    if (i >= NTAP * C_IN * C_OUT) return;
    int k    = i >> 12;
    int r    = i & 4095;
    int cin  = r >> 6;
    int cout = r & 63;
    float v = w[(cout * C_IN + cin) * NTAP + k];
    __nv_bfloat16 h = __float2bfloat16(v);
    __nv_bfloat16 l = __float2bfloat16(v - __bfloat162float(h));
    int o = (k * C_IN + cin) * WLD + cout;
    g_wh[o] = h;
    g_wl[o] = l;
}

// ---- main: gather -> bf16-split smem tiles -> wmma GEMM -> epilogue ----
__global__ __launch_bounds__(TPB)
void deform_mma(const float* __restrict__ offset,
                const float* __restrict__ bias,
                float* __restrict__ out) {
    __shared__ int   Pi[4 * TPX];
    __shared__ float Pa[4 * TPX];
    extern __shared__ char sm[];
    __nv_bfloat16* Ah = (__nv_bfloat16*)(sm + AH_OFF);
    __nv_bfloat16* Al = (__nv_bfloat16*)(sm + AL_OFF);
    __nv_bfloat16* Wh = (__nv_bfloat16*)(sm + WH_OFF);
    __nv_bfloat16* Wl = (__nv_bfloat16*)(sm + WL_OFF);

    const int tid = threadIdx.x;
    const int wid = tid >> 5;

    const int p0  = blockIdx.x * TPX;
    const int b   = p0 >> 15;
    const int rem = p0 & (HWO - 1);
    const int ho  = rem >> 8;
    const int wo0 = rem & (W_O - 1);

    const float* offb = offset + (size_t)b * 2 * NTAP * HWO + rem;
    const float* xtb  = g_xt + (size_t)b * HW * C_IN;

    // per-warp accumulators: 16 px x 64 cout, live across all taps
    wmma::fragment<wmma::accumulator, 16, 16, 16, float> acc[4];
#pragma unroll
    for (int n = 0; n < 4; n++) wmma::fill_fragment(acc[n], 0.0f);

    for (int k = 0; k < NTAP; k++) {
        __syncthreads();   // previous GEMM's smem reads done

        // stage this tap's weight tiles (linear copy, pad cols never read)
        {
            const uint4* sh = (const uint4*)(g_wh + k * C_IN * WLD);
            const uint4* sl = (const uint4*)(g_wl + k * C_IN * WLD);
            uint4* dh = (uint4*)Wh;
            uint4* dl = (uint4*)Wl;
#pragma unroll
            for (int i = tid; i < C_IN * WLD / 8; i += TPB) { dh[i] = sh[i]; dl[i] = sl[i]; }
        }

        // per-pixel bilinear params
        if (tid < TPX) {
            const float offy = __ldg(offb + (2 * k + 0) * HWO + tid);
            const float offx = __ldg(offb + (2 * k + 1) * HWO + tid);
            const float py = (float)(ho - 1 + k / 3) + offy;
            const float px = (float)(wo0 + tid - 1 + k % 3) + offx;
            const float y0f = floorf(py);
            const float x0f = floorf(px);
            const int   y0  = (int)y0f;
            const int   x0  = (int)x0f;
            const float wy  = py - y0f;
            const float wx  = px - x0f;
            const int   y1  = y0 + 1;
            const int   x1  = x0 + 1;
            const bool vy0 = (y0 >= 0) && (y0 < H_IN);
            const bool vy1 = (y1 >= 0) && (y1 < H_IN);
            const bool vx0 = (x0 >= 0) && (x0 < W_IN);
            const bool vx1 = (x1 >= 0) && (x1 < W_IN);
            const int cy0 = min(max(y0, 0), H_IN - 1);
            const int cy1 = min(max(y1, 0), H_IN - 1);
            const int cx0 = min(max(x0, 0), W_IN - 1);
            const int cx1 = min(max(x1, 0), W_IN - 1);
            Pi[0 * TPX + tid] = cy0 * W_IN + cx0;
            Pi[1 * TPX + tid] = cy0 * W_IN + cx1;
            Pi[2 * TPX + tid] = cy1 * W_IN + cx0;
            Pi[3 * TPX + tid] = cy1 * W_IN + cx1;
            Pa[0 * TPX + tid] = (vy0 && vx0) ? (1.0f - wy) * (1.0f - wx) : 0.0f;
            Pa[1 * TPX + tid] = (vy0 && vx1) ? (1.0f - wy) * wx          : 0.0f;
            Pa[2 * TPX + tid] = (vy1 && vx0) ? wy * (1.0f - wx)          : 0.0f;
            Pa[3 * TPX + tid] = (vy1 && vx1) ? wy * wx                   : 0.0f;
        }
        __syncthreads();

        // gather + bilinear + bf16 split -> Ah/Al[px][cin]
#pragma unroll
        for (int i = 0; i < 8; i++) {
            const int u  = tid + TPB * i;
            const int cg = u & 15;       // channel group of 4
            const int px = u >> 4;       // pixel in tile
            const int i00 = Pi[0 * TPX + px];
            const int i01 = Pi[1 * TPX + px];
            const int i10 = Pi[2 * TPX + px];
            const int i11 = Pi[3 * TPX + px];
            const float a00 = Pa[0 * TPX + px];
            const float a01 = Pa[1 * TPX + px];
            const float a10 = Pa[2 * TPX + px];
            const float a11 = Pa[3 * TPX + px];
            const float4 v00 = __ldg((const float4*)(xtb + (size_t)i00 * C_IN) + cg);
            const float4 v01 = __ldg((const float4*)(xtb + (size_t)i01 * C_IN) + cg);
            const float4 v10 = __ldg((const float4*)(xtb + (size_t)i10 * C_IN) + cg);
            const float4 v11 = __ldg((const float4*)(xtb + (size_t)i11 * C_IN) + cg);
            float4 r;
            r.x = fmaf(v00.x, a00, fmaf(v01.x, a01, fmaf(v10.x, a10, v11.x * a11)));
            r.y = fmaf(v00.y, a00, fmaf(v01.y, a01, fmaf(v10.y, a10, v11.y * a11)));
            r.z = fmaf(v00.z, a00, fmaf(v01.z, a01, fmaf(v10.z, a10, v11.z * a11)));
            r.w = fmaf(v00.w, a00, fmaf(v01.w, a01, fmaf(v10.w, a10, v11.w * a11)));

            __nv_bfloat162 h01 = __floats2bfloat162_rn(r.x, r.y);
            __nv_bfloat162 h23 = __floats2bfloat162_rn(r.z, r.w);
            __nv_bfloat162 l01 = __floats2bfloat162_rn(
                r.x - __bfloat162float(__low2bfloat16(h01)),
                r.y - __bfloat162float(__high2bfloat16(h01)));
            __nv_bfloat162 l23 = __floats2bfloat162_rn(
                r.z - __bfloat162float(__low2bfloat16(h23)),
                r.w - __bfloat162float(__high2bfloat16(h23)));

            const int o = px * ALD + cg * 4;
            uint2 hv, lv;
            hv.x = *(uint32_t*)&h01; hv.y = *(uint32_t*)&h23;
            lv.x = *(uint32_t*)&l01; lv.y = *(uint32_t*)&l23;
            *(uint2*)(Ah + o) = hv;
            *(uint2*)(Al + o) = lv;
        }
        __syncthreads();

        // GEMM: acc += Ah*Wh + Ah*Wl + Al*Wh   (warp = 16 px rows)
        const __nv_bfloat16* Ahw = Ah + wid * 16 * ALD;
        const __nv_bfloat16* Alw = Al + wid * 16 * ALD;
#pragma unroll
        for (int kc = 0; kc < 4; kc++) {
            wmma::fragment<wmma::matrix_a, 16, 16, 16, __nv_bfloat16, wmma::row_major> a_h, a_l;
            wmma::load_matrix_sync(a_h, Ahw + kc * 16, ALD);
            wmma::load_matrix_sync(a_l, Alw + kc * 16, ALD);
#pragma unroll
            for (int n = 0; n < 4; n++) {
                wmma::fragment<wmma::matrix_b, 16, 16, 16, __nv_bfloat16, wmma::row_major> b_h, b_l;
                wmma::load_matrix_sync(b_h, Wh + kc * 16 * WLD + n * 16, WLD);
                wmma::load_matrix_sync(b_l, Wl + kc * 16 * WLD + n * 16, WLD);
                wmma::mma_sync(acc[n], a_h, b_h, acc[n]);
                wmma::mma_sync(acc[n], a_h, b_l, acc[n]);
                wmma::mma_sync(acc[n], a_l, b_h, acc[n]);
            }
        }
    }

    // epilogue: dump accum to smem (reuse A region), then coalesced global write
    __syncthreads();
    float* Osm = (float*)sm;    // [128][OLD]
#pragma unroll
    for (int n = 0; n < 4; n++)
        wmma::store_matrix_sync(Osm + wid * 16 * OLD + n * 16, acc[n], OLD,
                                wmma::mem_row_major);
    __syncthreads();

    float* ob = out + (size_t)b * C_OUT * HWO + rem;
#pragma unroll
    for (int i = 0; i < 32; i++) {
        const int u  = tid + TPB * i;
        const int c  = u >> 7;
        const int px = u & 127;
        ob[(size_t)c * HWO + px] = Osm[px * OLD + c] + __ldg(bias + c);
    }
}

extern "C" void kernel_launch(void* const* d_in, const int* in_sizes, int n_in,
                              void* d_out, int out_size) {
    const float* x      = (const float*)d_in[0];
    const float* offset = (const float*)d_in[1];
    const float* weight = (const float*)d_in[2];
    const float* bias   = (const float*)d_in[3];
    float* out = (float*)d_out;
    (void)in_sizes; (void)n_in; (void)out_size;

    cudaFuncSetAttribute(deform_mma,
                         cudaFuncAttributeMaxDynamicSharedMemorySize, SMEM_BYTES);

    dim3 tg(HW / 32, C_IN / 32, B_N);
    transpose_nchw_nhwc<<<tg, dim3(32, 8)>>>(x);
    prep_weights<<<(NTAP * C_IN * C_OUT + 255) / 256, 256>>>(weight);
    deform_mma<<<NPIX / TPX, TPB, SMEM_BYTES>>>(offset, bias, out);
}

// round 6
// speedup vs baseline: 1.5811x; 1.1019x over previous
#include <cuda_runtime.h>
#include <cuda_bf16.h>
#include <mma.h>
#include <cstdint>

using namespace nvcuda;

// Deformable conv2d: B=2, CIN=64, H=128, W=256, COUT=64, K=3, s=1, p=1, d=1
#define B_N   2
#define C_IN  64
#define H_IN  128
#define W_IN  256
#define C_OUT 64
#define NTAP  9
#define H_O   128
#define W_O   256
#define HW    (H_IN * W_IN)     // 32768
#define HWO   (H_O * W_O)       // 32768
#define NPIX  (B_N * HWO)       // 65536

#define TPX   128               // pixels (M) per CTA tile
#define TPB   256               // 8 warps

#define ALD   72                // A smem leading dim (bf16), mult of 8
#define WLD   72                // W smem leading dim

// dynamic smem (bytes):
//   Ah 18432 | Al 18432 | Wbuf0 (hi 9216 + lo 9216) | Wbuf1 (hi + lo)
#define AH_OFF   0
#define AL_OFF   18432
#define W_OFF    36864
#define W_TAP_B  18432          // hi+lo per tap
#define SMEM_BYTES (36864 + 2 * W_TAP_B)   // 73728

__device__ float g_xt[(size_t)B_N * HW * C_IN];          // NHWC fp32, 16 MB
// per tap: hi tile [cin][WLD] then lo tile [cin][WLD], contiguous 18432 B
__device__ __nv_bfloat16 g_w2[NTAP * 2 * C_IN * WLD];

__device__ __forceinline__ uint32_t smem_u32(const void* p) {
    uint32_t a;
    asm("{ .reg .u64 t; cvta.to.shared.u64 t, %1; cvt.u32.u64 %0, t; }" : "=r"(a) : "l"(p));
    return a;
}
__device__ __forceinline__ void cp_async16(uint32_t dst, const void* src) {
    asm volatile("cp.async.cg.shared.global [%0], [%1], 16;" :: "r"(dst), "l"(src));
}
#define CP_COMMIT() asm volatile("cp.async.commit_group;" ::: "memory")
#define CP_WAIT1()  asm volatile("cp.async.wait_group 1;" ::: "memory")

// ---- NCHW -> NHWC fp32 transpose ----
__global__ void transpose_nchw_nhwc(const float* __restrict__ x) {
    __shared__ float tile[32][33];
    const int b   = blockIdx.z;
    const int c0  = blockIdx.y * 32;
    const int hw0 = blockIdx.x * 32;
    const int tx  = threadIdx.x;
    const int ty  = threadIdx.y;   // block (32, 8)
    const float* xb = x + (size_t)b * C_IN * HW;
    float* xtb = g_xt + (size_t)b * HW * C_IN;
#pragma unroll
    for (int j = 0; j < 32; j += 8)
        tile[ty + j][tx] = xb[(size_t)(c0 + ty + j) * HW + hw0 + tx];
    __syncthreads();
#pragma unroll
    for (int j = 0; j < 32; j += 8)
        xtb[(size_t)(hw0 + ty + j) * C_IN + c0 + tx] = tile[tx][ty + j];
}

// ---- weight [cout][cin][k] -> bf16 hi/lo [k][{hi,lo}][cin][cout(+pad)] ----
__global__ void prep_weights(const float* __restrict__ w) {
    int i = blockIdx.x * 256 + threadIdx.x;
    if (i >= NTAP * C_IN * C_OUT) return;
    int k    = i >> 12;
    int r    = i & 4095;
    int cin  = r >> 6;
    int cout = r & 63;
    float v = w[(cout * C_IN + cin) * NTAP + k];
    __nv_bfloat16 h = __float2bfloat16(v);
    __nv_bfloat16 l = __float2bfloat16(v - __bfloat162float(h));
    __nv_bfloat16* base = g_w2 + (size_t)k * 2 * C_IN * WLD;
    base[cin * WLD + cout]               = h;
    base[C_IN * WLD + cin * WLD + cout]  = l;
}

// ---- main ----
__global__ __launch_bounds__(TPB, 2)
void deform_mma(const float* __restrict__ offset,
                const float* __restrict__ bias,
                float* __restrict__ out) {
    __shared__ int   Pi[4 * TPX];
    __shared__ float Pa[4 * TPX];
    __shared__ float Bsm[16 * 68];      // bias broadcast tile [16 rows][64+pad]
    extern __shared__ char sm[];
    __nv_bfloat16* Ah = (__nv_bfloat16*)(sm + AH_OFF);
    __nv_bfloat16* Al = (__nv_bfloat16*)(sm + AL_OFF);

    const int tid = threadIdx.x;
    const int wid = tid >> 5;

    const int p0  = blockIdx.x * TPX;
    const int b   = p0 >> 15;
    const int rem = p0 & (HWO - 1);
    const int ho  = rem >> 8;
    const int wo0 = rem & (W_O - 1);

    const float* offb = offset + (size_t)b * 2 * NTAP * HWO + rem;
    const float* xtb  = g_xt + (size_t)b * HW * C_IN;
    const uint32_t wsm = smem_u32(sm + W_OFF);

    // prefetch tap-0 weights (group g0)
    {
        const char* src = (const char*)(g_w2);
        for (int i = tid; i < W_TAP_B / 16; i += TPB)
            cp_async16(wsm + i * 16, src + i * 16);
        CP_COMMIT();
    }
    // bias broadcast tile
    for (int i = tid; i < 16 * 64; i += TPB) {
        int r = i >> 6, c = i & 63;
        Bsm[r * 68 + c] = __ldg(bias + c);
    }
    __syncthreads();

    // accumulators preloaded with bias
    wmma::fragment<wmma::accumulator, 16, 16, 16, float> acc[4];
#pragma unroll
    for (int n = 0; n < 4; n++)
        wmma::load_matrix_sync(acc[n], Bsm + n * 16, 68, wmma::mem_row_major);

    for (int k = 0; k < NTAP; k++) {
        __syncthreads();   // previous GEMM's A/param reads done

        // per-pixel bilinear params
        if (tid < TPX) {
            const float offy = __ldg(offb + (2 * k + 0) * HWO + tid);
            const float offx = __ldg(offb + (2 * k + 1) * HWO + tid);
            const float py = (float)(ho - 1 + k / 3) + offy;
            const float px = (float)(wo0 + tid - 1 + k % 3) + offx;
            const float y0f = floorf(py);
            const float x0f = floorf(px);
            const int   y0  = (int)y0f;
            const int   x0  = (int)x0f;
            const float wy  = py - y0f;
            const float wx  = px - x0f;
            const int   y1  = y0 + 1;
            const int   x1  = x0 + 1;
            const bool vy0 = (y0 >= 0) && (y0 < H_IN);
            const bool vy1 = (y1 >= 0) && (y1 < H_IN);
            const bool vx0 = (x0 >= 0) && (x0 < W_IN);
            const bool vx1 = (x1 >= 0) && (x1 < W_IN);
            const int cy0 = min(max(y0, 0), H_IN - 1);
            const int cy1 = min(max(y1, 0), H_IN - 1);
            const int cx0 = min(max(x0, 0), W_IN - 1);
            const int cx1 = min(max(x1, 0), W_IN - 1);
            Pi[0 * TPX + tid] = cy0 * W_IN + cx0;
            Pi[1 * TPX + tid] = cy0 * W_IN + cx1;
            Pi[2 * TPX + tid] = cy1 * W_IN + cx0;
            Pi[3 * TPX + tid] = cy1 * W_IN + cx1;
            Pa[0 * TPX + tid] = (vy0 && vx0) ? (1.0f - wy) * (1.0f - wx) : 0.0f;
            Pa[1 * TPX + tid] = (vy0 && vx1) ? (1.0f - wy) * wx          : 0.0f;
            Pa[2 * TPX + tid] = (vy1 && vx0) ? wy * (1.0f - wx)          : 0.0f;
            Pa[3 * TPX + tid] = (vy1 && vx1) ? wy * wx                   : 0.0f;
        }
        __syncthreads();

        // gather + bilinear + bf16 split -> Ah/Al[px][cin]
#pragma unroll
        for (int i = 0; i < 8; i++) {
            const int u  = tid + TPB * i;
            const int cg = u & 15;       // channel group of 4
            const int px = u >> 4;       // pixel in tile
            const int i00 = Pi[0 * TPX + px];
            const int i01 = Pi[1 * TPX + px];
            const int i10 = Pi[2 * TPX + px];
            const int i11 = Pi[3 * TPX + px];
            const float a00 = Pa[0 * TPX + px];
            const float a01 = Pa[1 * TPX + px];
            const float a10 = Pa[2 * TPX + px];
            const float a11 = Pa[3 * TPX + px];
            const float4 v00 = __ldg((const float4*)(xtb + (size_t)i00 * C_IN) + cg);
            const float4 v01 = __ldg((const float4*)(xtb + (size_t)i01 * C_IN) + cg);
            const float4 v10 = __ldg((const float4*)(xtb + (size_t)i10 * C_IN) + cg);
            const float4 v11 = __ldg((const float4*)(xtb + (size_t)i11 * C_IN) + cg);
            float4 r;
            r.x = fmaf(v00.x, a00, fmaf(v01.x, a01, fmaf(v10.x, a10, v11.x * a11)));
            r.y = fmaf(v00.y, a00, fmaf(v01.y, a01, fmaf(v10.y, a10, v11.y * a11)));
            r.z = fmaf(v00.z, a00, fmaf(v01.z, a01, fmaf(v10.z, a10, v11.z * a11)));
            r.w = fmaf(v00.w, a00, fmaf(v01.w, a01, fmaf(v10.w, a10, v11.w * a11)));

            __nv_bfloat162 h01 = __floats2bfloat162_rn(r.x, r.y);
            __nv_bfloat162 h23 = __floats2bfloat162_rn(r.z, r.w);
            __nv_bfloat162 l01 = __floats2bfloat162_rn(
                r.x - __bfloat162float(__low2bfloat16(h01)),
                r.y - __bfloat162float(__high2bfloat16(h01)));
            __nv_bfloat162 l23 = __floats2bfloat162_rn(
                r.z - __bfloat162float(__low2bfloat16(h23)),
                r.w - __bfloat162float(__high2bfloat16(h23)));

            const int o = px * ALD + cg * 4;
            uint2 hv, lv;
            hv.x = *(uint32_t*)&h01; hv.y = *(uint32_t*)&h23;
            lv.x = *(uint32_t*)&l01; lv.y = *(uint32_t*)&l23;
            *(uint2*)(Ah + o) = hv;
            *(uint2*)(Al + o) = lv;
        }

        // prefetch next tap's weights into the other W buffer
        {
            const int kn = k + 1;
            if (kn < NTAP) {
                const char* src = (const char*)(g_w2 + (size_t)kn * 2 * C_IN * WLD);
                const uint32_t dst = wsm + (kn & 1) * W_TAP_B;
                for (int i = tid; i < W_TAP_B / 16; i += TPB)
                    cp_async16(dst + i * 16, src + i * 16);
            }
            CP_COMMIT();            // empty group when kn==NTAP (keeps count math)
        }
        CP_WAIT1();                 // this tap's weights resident (own groups)
        __syncthreads();            // ...across all threads

        // GEMM: acc += Ah*Wh + Ah*Wl + Al*Wh   (warp = 16 px rows)
        const __nv_bfloat16* Wh = (const __nv_bfloat16*)(sm + W_OFF + (k & 1) * W_TAP_B);
        const __nv_bfloat16* Wl = Wh + C_IN * WLD;
        const __nv_bfloat16* Ahw = Ah + wid * 16 * ALD;
        const __nv_bfloat16* Alw = Al + wid * 16 * ALD;
#pragma unroll
        for (int kc = 0; kc < 4; kc++) {
            wmma::fragment<wmma::matrix_a, 16, 16, 16, __nv_bfloat16, wmma::row_major> a_h, a_l;
            wmma::load_matrix_sync(a_h, Ahw + kc * 16, ALD);
            wmma::load_matrix_sync(a_l, Alw + kc * 16, ALD);
#pragma unroll
            for (int n = 0; n < 4; n++) {
                wmma::fragment<wmma::matrix_b, 16, 16, 16, __nv_bfloat16, wmma::row_major> b_h, b_l;
                wmma::load_matrix_sync(b_h, Wh + kc * 16 * WLD + n * 16, WLD);
                wmma::load_matrix_sync(b_l, Wl + kc * 16 * WLD + n * 16, WLD);
                wmma::mma_sync(acc[n], a_h, b_h, acc[n]);
                wmma::mma_sync(acc[n], a_h, b_l, acc[n]);
                wmma::mma_sync(acc[n], a_l, b_h, acc[n]);
            }
        }
    }

    // epilogue: direct col-major store -> out[b][cout][px], bias already in acc
    float* ob = out + (size_t)b * C_OUT * HWO + rem + wid * 16;
#pragma unroll
    for (int n = 0; n < 4; n++)
        wmma::store_matrix_sync(ob + (size_t)(n * 16) * HWO, acc[n], HWO,
                                wmma::mem_col_major);
}

extern "C" void kernel_launch(void* const* d_in, const int* in_sizes, int n_in,
                              void* d_out, int out_size) {
    const float* x      = (const float*)d_in[0];
    const float* offset = (const float*)d_in[1];
    const float* weight = (const float*)d_in[2];
    const float* bias   = (const float*)d_in[3];
    float* out = (float*)d_out;
    (void)in_sizes; (void)n_in; (void)out_size;

    cudaFuncSetAttribute(deform_mma,
                         cudaFuncAttributeMaxDynamicSharedMemorySize, SMEM_BYTES);

    dim3 tg(HW / 32, C_IN / 32, B_N);
    transpose_nchw_nhwc<<<tg, dim3(32, 8)>>>(x);
    prep_weights<<<(NTAP * C_IN * C_OUT + 255) / 256, 256>>>(weight);
    deform_mma<<<NPIX / TPX, TPB, SMEM_BYTES>>>(offset, bias, out);
}

// round 7
// speedup vs baseline: 2.3201x; 1.4675x over previous
#include <cuda_runtime.h>
#include <cuda_fp16.h>
#include <mma.h>
#include <cstdint>

using namespace nvcuda;

// Deformable conv2d: B=2, CIN=64, H=128, W=256, COUT=64, K=3, s=1, p=1, d=1
#define B_N   2
#define C_IN  64
#define H_IN  128
#define W_IN  256
#define C_OUT 64
#define NTAP  9
#define H_O   128
#define W_O   256
#define HW    (H_IN * W_IN)     // 32768
#define HWO   (H_O * W_O)       // 32768
#define NPIX  (B_N * HWO)       // 65536

#define TPX   128               // pixels (M) per CTA tile
#define TPB   256               // 8 warps

#define ALD   72                // A smem leading dim (fp16), mult of 8
#define WLD   72                // W smem leading dim

// dynamic smem (bytes): Ah 18432 | Al 18432 | Wbuf0 (hi+lo) | Wbuf1 (hi+lo)
#define AH_OFF   0
#define AL_OFF   18432
#define W_OFF    36864
#define W_TAP_B  18432          // hi (64*72*2) + lo per tap
#define SMEM_BYTES (36864 + 2 * W_TAP_B)   // 73728

__device__ __half g_xh[(size_t)B_N * HW * C_IN];   // NHWC fp16 x, 8 MB
// per tap: hi tile [cin][WLD] then lo tile [cin][WLD], contiguous 18432 B
__device__ __half g_w2[NTAP * 2 * C_IN * WLD];

__device__ __forceinline__ uint32_t smem_u32(const void* p) {
    uint32_t a;
    asm("{ .reg .u64 t; cvta.to.shared.u64 t, %1; cvt.u32.u64 %0, t; }" : "=r"(a) : "l"(p));
    return a;
}
__device__ __forceinline__ void cp_async16(uint32_t dst, const void* src) {
    asm volatile("cp.async.cg.shared.global [%0], [%1], 16;" :: "r"(dst), "l"(src));
}
#define CP_COMMIT() asm volatile("cp.async.commit_group;" ::: "memory")
#define CP_WAIT1()  asm volatile("cp.async.wait_group 1;" ::: "memory")

// ---- NCHW fp32 -> NHWC fp16 transpose ----
__global__ void transpose_h(const float* __restrict__ x) {
    __shared__ float tile[32][33];
    const int b   = blockIdx.z;
    const int c0  = blockIdx.y * 32;
    const int hw0 = blockIdx.x * 32;
    const int tx  = threadIdx.x;
    const int ty  = threadIdx.y;   // block (32, 8)
    const float* xb = x + (size_t)b * C_IN * HW;
    __half* xtb = g_xh + (size_t)b * HW * C_IN;
#pragma unroll
    for (int j = 0; j < 32; j += 8)
        tile[ty + j][tx] = xb[(size_t)(c0 + ty + j) * HW + hw0 + tx];
    __syncthreads();
#pragma unroll
    for (int j = 0; j < 32; j += 8)
        xtb[(size_t)(hw0 + ty + j) * C_IN + c0 + tx] = __float2half_rn(tile[tx][ty + j]);
}

// ---- weight [cout][cin][k] -> fp16 hi/lo [k][{hi,lo}][cin][cout(+pad)] ----
__global__ void prep_weights(const float* __restrict__ w) {
    int i = blockIdx.x * 256 + threadIdx.x;
    if (i >= NTAP * C_IN * C_OUT) return;
    int k    = i >> 12;
    int r    = i & 4095;
    int cin  = r >> 6;
    int cout = r & 63;
    float v = w[(cout * C_IN + cin) * NTAP + k];
    __half h = __float2half_rn(v);
    __half l = __float2half_rn(v - __half2float(h));
    __half* base = g_w2 + (size_t)k * 2 * C_IN * WLD;
    base[cin * WLD + cout]              = h;
    base[C_IN * WLD + cin * WLD + cout] = l;
}

// ---- main ----
__global__ __launch_bounds__(TPB, 2)
void deform_mma(const float* __restrict__ offset,
                const float* __restrict__ bias,
                float* __restrict__ out) {
    __shared__ int   Pi[4 * TPX];
    __shared__ float Pa[4 * TPX];
    __shared__ float Bsm[16 * 68];      // bias broadcast tile [16 rows][64+pad]
    extern __shared__ char sm[];
    __half* Ah = (__half*)(sm + AH_OFF);
    __half* Al = (__half*)(sm + AL_OFF);

    const int tid = threadIdx.x;
    const int wid = tid >> 5;

    const int p0  = blockIdx.x * TPX;
    const int b   = p0 >> 15;
    const int rem = p0 & (HWO - 1);
    const int ho  = rem >> 8;
    const int wo0 = rem & (W_O - 1);

    const float* offb = offset + (size_t)b * 2 * NTAP * HWO + rem;
    const __half* xhb = g_xh + (size_t)b * HW * C_IN;
    const uint32_t wsm = smem_u32(sm + W_OFF);

    // prefetch tap-0 weights
    {
        const char* src = (const char*)(g_w2);
        for (int i = tid; i < W_TAP_B / 16; i += TPB)
            cp_async16(wsm + i * 16, src + i * 16);
        CP_COMMIT();
    }
    // bias broadcast tile
    for (int i = tid; i < 16 * 64; i += TPB) {
        int r = i >> 6, c = i & 63;
        Bsm[r * 68 + c] = __ldg(bias + c);
    }
    __syncthreads();

    // accumulators preloaded with bias
    wmma::fragment<wmma::accumulator, 16, 16, 16, float> acc[4];
#pragma unroll
    for (int n = 0; n < 4; n++)
        wmma::load_matrix_sync(acc[n], Bsm + n * 16, 68, wmma::mem_row_major);

    for (int k = 0; k < NTAP; k++) {
        __syncthreads();   // previous GEMM's A/param reads done

        // per-pixel bilinear params
        if (tid < TPX) {
            const float offy = __ldg(offb + (2 * k + 0) * HWO + tid);
            const float offx = __ldg(offb + (2 * k + 1) * HWO + tid);
            const float py = (float)(ho - 1 + k / 3) + offy;
            const float px = (float)(wo0 + tid - 1 + k % 3) + offx;
            const float y0f = floorf(py);
            const float x0f = floorf(px);
            const int   y0  = (int)y0f;
            const int   x0  = (int)x0f;
            const float wy  = py - y0f;
            const float wx  = px - x0f;
            const int   y1  = y0 + 1;
            const int   x1  = x0 + 1;
            const bool vy0 = (y0 >= 0) && (y0 < H_IN);
            const bool vy1 = (y1 >= 0) && (y1 < H_IN);
            const bool vx0 = (x0 >= 0) && (x0 < W_IN);
            const bool vx1 = (x1 >= 0) && (x1 < W_IN);
            const int cy0 = min(max(y0, 0), H_IN - 1);
            const int cy1 = min(max(y1, 0), H_IN - 1);
            const int cx0 = min(max(x0, 0), W_IN - 1);
            const int cx1 = min(max(x1, 0), W_IN - 1);
            Pi[0 * TPX + tid] = cy0 * W_IN + cx0;
            Pi[1 * TPX + tid] = cy0 * W_IN + cx1;
            Pi[2 * TPX + tid] = cy1 * W_IN + cx0;
            Pi[3 * TPX + tid] = cy1 * W_IN + cx1;
            Pa[0 * TPX + tid] = (vy0 && vx0) ? (1.0f - wy) * (1.0f - wx) : 0.0f;
            Pa[1 * TPX + tid] = (vy0 && vx1) ? (1.0f - wy) * wx          : 0.0f;
            Pa[2 * TPX + tid] = (vy1 && vx0) ? wy * (1.0f - wx)          : 0.0f;
            Pa[3 * TPX + tid] = (vy1 && vx1) ? wy * wx                   : 0.0f;
        }
        __syncthreads();

        // gather(fp16) + fp32 bilinear + fp16 split -> Ah/Al[px][cin]
        // unit: 8 channels (16 B). 128 px * 8 groups = 1024 units, 4 per thread.
#pragma unroll
        for (int i = 0; i < 4; i++) {
            const int u  = tid + TPB * i;
            const int cg = u & 7;        // channel group of 8
            const int px = u >> 3;       // pixel in tile
            const int i00 = Pi[0 * TPX + px];
            const int i01 = Pi[1 * TPX + px];
            const int i10 = Pi[2 * TPX + px];
            const int i11 = Pi[3 * TPX + px];
            const float a00 = Pa[0 * TPX + px];
            const float a01 = Pa[1 * TPX + px];
            const float a10 = Pa[2 * TPX + px];
            const float a11 = Pa[3 * TPX + px];
            const uint4 v00 = __ldg((const uint4*)(xhb + (size_t)i00 * C_IN) + cg);
            const uint4 v01 = __ldg((const uint4*)(xhb + (size_t)i01 * C_IN) + cg);
            const uint4 v10 = __ldg((const uint4*)(xhb + (size_t)i10 * C_IN) + cg);
            const uint4 v11 = __ldg((const uint4*)(xhb + (size_t)i11 * C_IN) + cg);

            uint4 hq, lq;
            const __half2* p00 = (const __half2*)&v00;
            const __half2* p01 = (const __half2*)&v01;
            const __half2* p10 = (const __half2*)&v10;
            const __half2* p11 = (const __half2*)&v11;
            __half2* hh = (__half2*)&hq;
            __half2* ll = (__half2*)&lq;
#pragma unroll
            for (int j = 0; j < 4; j++) {
                const float2 c00 = __half22float2(p00[j]);
                const float2 c01 = __half22float2(p01[j]);
                const float2 c10 = __half22float2(p10[j]);
                const float2 c11 = __half22float2(p11[j]);
                float2 r;
                r.x = fmaf(c00.x, a00, fmaf(c01.x, a01, fmaf(c10.x, a10, c11.x * a11)));
                r.y = fmaf(c00.y, a00, fmaf(c01.y, a01, fmaf(c10.y, a10, c11.y * a11)));
                const __half2 h = __float22half2_rn(r);
                const float2 hf = __half22float2(h);
                float2 res;
                res.x = r.x - hf.x;
                res.y = r.y - hf.y;
                hh[j] = h;
                ll[j] = __float22half2_rn(res);
            }
            const int o = px * ALD + cg * 8;
            *(uint4*)(Ah + o) = hq;
            *(uint4*)(Al + o) = lq;
        }

        // prefetch next tap's weights into the other W buffer
        {
            const int kn = k + 1;
            if (kn < NTAP) {
                const char* src = (const char*)(g_w2 + (size_t)kn * 2 * C_IN * WLD);
                const uint32_t dst = wsm + (kn & 1) * W_TAP_B;
                for (int i = tid; i < W_TAP_B / 16; i += TPB)
                    cp_async16(dst + i * 16, src + i * 16);
            }
            CP_COMMIT();
        }
        CP_WAIT1();
        __syncthreads();

        // GEMM: acc += Ah*Wh + Ah*Wl + Al*Wh   (warp = 16 px rows)
        const __half* Wh = (const __half*)(sm + W_OFF + (k & 1) * W_TAP_B);
        const __half* Wl = Wh + C_IN * WLD;
        const __half* Ahw = Ah + wid * 16 * ALD;
        const __half* Alw = Al + wid * 16 * ALD;
#pragma unroll
        for (int kc = 0; kc < 4; kc++) {
            wmma::fragment<wmma::matrix_a, 16, 16, 16, __half, wmma::row_major> a_h, a_l;
            wmma::load_matrix_sync(a_h, Ahw + kc * 16, ALD);
            wmma::load_matrix_sync(a_l, Alw + kc * 16, ALD);
#pragma unroll
            for (int n = 0; n < 4; n++) {
                wmma::fragment<wmma::matrix_b, 16, 16, 16, __half, wmma::row_major> b_h, b_l;
                wmma::load_matrix_sync(b_h, Wh + kc * 16 * WLD + n * 16, WLD);
                wmma::load_matrix_sync(b_l, Wl + kc * 16 * WLD + n * 16, WLD);
                wmma::mma_sync(acc[n], a_h, b_h, acc[n]);
                wmma::mma_sync(acc[n], a_h, b_l, acc[n]);
                wmma::mma_sync(acc[n], a_l, b_h, acc[n]);
            }
        }
    }

    // epilogue: direct col-major store -> out[b][cout][px], bias already in acc
    float* ob = out + (size_t)b * C_OUT * HWO + rem + wid * 16;
#pragma unroll
    for (int n = 0; n < 4; n++)
        wmma::store_matrix_sync(ob + (size_t)(n * 16) * HWO, acc[n], HWO,
                                wmma::mem_col_major);
}

extern "C" void kernel_launch(void* const* d_in, const int* in_sizes, int n_in,
                              void* d_out, int out_size) {
    const float* x      = (const float*)d_in[0];
    const float* offset = (const float*)d_in[1];
    const float* weight = (const float*)d_in[2];
    const float* bias   = (const float*)d_in[3];
    float* out = (float*)d_out;
    (void)in_sizes; (void)n_in; (void)out_size;

    cudaFuncSetAttribute(deform_mma,
                         cudaFuncAttributeMaxDynamicSharedMemorySize, SMEM_BYTES);

    dim3 tg(HW / 32, C_IN / 32, B_N);
    transpose_h<<<tg, dim3(32, 8)>>>(x);
    prep_weights<<<(NTAP * C_IN * C_OUT + 255) / 256, 256>>>(weight);
    deform_mma<<<NPIX / TPX, TPB, SMEM_BYTES>>>(offset, bias, out);
}

// round 8
// speedup vs baseline: 2.8655x; 1.2351x over previous
#include <cuda_runtime.h>
#include <cuda_fp16.h>
#include <mma.h>
#include <cstdint>

using namespace nvcuda;

// Deformable conv2d: B=2, CIN=64, H=128, W=256, COUT=64, K=3, s=1, p=1, d=1
#define B_N   2
#define C_IN  64
#define H_IN  128
#define W_IN  256
#define C_OUT 64
#define NTAP  9
#define H_O   128
#define W_O   256
#define HW    (H_IN * W_IN)     // 32768
#define HWO   (H_O * W_O)       // 32768
#define NPIX  (B_N * HWO)       // 65536

#define TPX   128               // pixels (M) per CTA tile
#define TPB   256               // 8 warps

#define ALD   72                // A smem leading dim (fp16), mult of 8
#define WLD   72                // W smem leading dim

// dynamic smem (bytes):
//   A bufs : 2 * 128*72*2 = 36864
//   W bufs : 2 * (hi+lo = 2*64*72*2) = 36864
//   Pw     : float4 * 128*9 = 18432
//   Pidx   : ushort4 * 128*9 = 9216
#define A_OFF    0
#define A_BUF_B  18432
#define W_OFF    36864
#define W_TAP_B  18432
#define PW_OFF   73728
#define PI_OFF   92160
#define SMEM_BYTES 101376

__device__ __half g_xh[(size_t)B_N * HW * C_IN];   // NHWC fp16 x, 8 MB
// per tap: hi tile [cin][WLD] then lo tile [cin][WLD]
__device__ __half g_w2[NTAP * 2 * C_IN * WLD];

__device__ __forceinline__ uint32_t smem_u32(const void* p) {
    uint32_t a;
    asm("{ .reg .u64 t; cvta.to.shared.u64 t, %1; cvt.u32.u64 %0, t; }" : "=r"(a) : "l"(p));
    return a;
}
__device__ __forceinline__ void cp_async16(uint32_t dst, const void* src) {
    asm volatile("cp.async.cg.shared.global [%0], [%1], 16;" :: "r"(dst), "l"(src));
}
#define CP_COMMIT() asm volatile("cp.async.commit_group;" ::: "memory")
#define CP_WAIT0()  asm volatile("cp.async.wait_group 0;" ::: "memory")

// ---- NCHW fp32 -> NHWC fp16 transpose ----
__global__ void transpose_h(const float* __restrict__ x) {
    __shared__ float tile[32][33];
    const int b   = blockIdx.z;
    const int c0  = blockIdx.y * 32;
    const int hw0 = blockIdx.x * 32;
    const int tx  = threadIdx.x;
    const int ty  = threadIdx.y;   // block (32, 8)
    const float* xb = x + (size_t)b * C_IN * HW;
    __half* xtb = g_xh + (size_t)b * HW * C_IN;
#pragma unroll
    for (int j = 0; j < 32; j += 8)
        tile[ty + j][tx] = xb[(size_t)(c0 + ty + j) * HW + hw0 + tx];
    __syncthreads();
#pragma unroll
    for (int j = 0; j < 32; j += 8)
        xtb[(size_t)(hw0 + ty + j) * C_IN + c0 + tx] = __float2half_rn(tile[tx][ty + j]);
}

// ---- weight [cout][cin][k] -> fp16 hi/lo [k][{hi,lo}][cin][cout(+pad)] ----
__global__ void prep_weights(const float* __restrict__ w) {
    int i = blockIdx.x * 256 + threadIdx.x;
    if (i >= NTAP * C_IN * C_OUT) return;
    int k    = i >> 12;
    int r    = i & 4095;
    int cin  = r >> 6;
    int cout = r & 63;
    float v = w[(cout * C_IN + cin) * NTAP + k];
    __half h = __float2half_rn(v);
    __half l = __float2half_rn(v - __half2float(h));
    __half* base = g_w2 + (size_t)k * 2 * C_IN * WLD;
    base[cin * WLD + cout]              = h;
    base[C_IN * WLD + cin * WLD + cout] = l;
}

// ---- main ----
__global__ __launch_bounds__(TPB, 2)
void deform_mma(const float* __restrict__ offset,
                const float* __restrict__ bias,
                float* __restrict__ out) {
    __shared__ float Bsm[16 * 68];
    extern __shared__ char sm[];
    float4*  Pw = (float4*)(sm + PW_OFF);     // [tap*128+px] corner weights
    ushort4* Pidx = (ushort4*)(sm + PI_OFF);  // [tap*128+px] corner indices

    const int tid = threadIdx.x;
    const int wid = tid >> 5;

    const int p0  = blockIdx.x * TPX;
    const int b   = p0 >> 15;
    const int rem = p0 & (HWO - 1);
    const int ho  = rem >> 8;
    const int wo0 = rem & (W_O - 1);

    const float* offb = offset + (size_t)b * 2 * NTAP * HWO + rem;
    const __half* xhb = g_xh + (size_t)b * HW * C_IN;
    const uint32_t wsm = smem_u32(sm + W_OFF);

    // prefetch tap-0 weights
    {
        const char* src = (const char*)(g_w2);
        for (int i = tid; i < W_TAP_B / 16; i += TPB)
            cp_async16(wsm + i * 16, src + i * 16);
        CP_COMMIT();
    }
    // bias broadcast tile
    for (int i = tid; i < 16 * 64; i += TPB) {
        int r = i >> 6, c = i & 63;
        Bsm[r * 68 + c] = __ldg(bias + c);
    }

    // precompute bilinear params for ALL taps: 9*128 units
    for (int u = tid; u < NTAP * TPX; u += TPB) {
        const int k  = u >> 7;
        const int p  = u & 127;
        const float offy = __ldg(offb + (2 * k + 0) * HWO + p);
        const float offx = __ldg(offb + (2 * k + 1) * HWO + p);
        const float py = (float)(ho - 1 + k / 3) + offy;
        const float px = (float)(wo0 + p - 1 + k % 3) + offx;
        const float y0f = floorf(py);
        const float x0f = floorf(px);
        const int   y0  = (int)y0f;
        const int   x0  = (int)x0f;
        const float wy  = py - y0f;
        const float wx  = px - x0f;
        const int   y1  = y0 + 1;
        const int   x1  = x0 + 1;
        const bool vy0 = (y0 >= 0) && (y0 < H_IN);
        const bool vy1 = (y1 >= 0) && (y1 < H_IN);
        const bool vx0 = (x0 >= 0) && (x0 < W_IN);
        const bool vx1 = (x1 >= 0) && (x1 < W_IN);
        const int cy0 = min(max(y0, 0), H_IN - 1);
        const int cy1 = min(max(y1, 0), H_IN - 1);
        const int cx0 = min(max(x0, 0), W_IN - 1);
        const int cx1 = min(max(x1, 0), W_IN - 1);
        ushort4 pi;
        pi.x = (unsigned short)(cy0 * W_IN + cx0);
        pi.y = (unsigned short)(cy0 * W_IN + cx1);
        pi.z = (unsigned short)(cy1 * W_IN + cx0);
        pi.w = (unsigned short)(cy1 * W_IN + cx1);
        float4 pw;
        pw.x = (vy0 && vx0) ? (1.0f - wy) * (1.0f - wx) : 0.0f;
        pw.y = (vy0 && vx1) ? (1.0f - wy) * wx          : 0.0f;
        pw.z = (vy1 && vx0) ? wy * (1.0f - wx)          : 0.0f;
        pw.w = (vy1 && vx1) ? wy * wx                   : 0.0f;
        Pidx[u] = pi;
        Pw[u]   = pw;
    }
    __syncthreads();

    // accumulators preloaded with bias
    wmma::fragment<wmma::accumulator, 16, 16, 16, float> acc[4];
#pragma unroll
    for (int n = 0; n < 4; n++)
        wmma::load_matrix_sync(acc[n], Bsm + n * 16, 68, wmma::mem_row_major);

    // fill one tap into a given A buffer: 1024 units (px, 8-ch group)
    auto fill_tap = [&](int k, int buf) {
        __half* A = (__half*)(sm + A_OFF + buf * A_BUF_B);
#pragma unroll
        for (int i = 0; i < 4; i++) {
            const int u  = tid + TPB * i;
            const int cg = u & 7;        // channel group of 8
            const int px = u >> 3;       // pixel in tile
            const ushort4 pi = Pidx[k * TPX + px];
            const float4  pa = Pw[k * TPX + px];
            const uint4 v00 = __ldg((const uint4*)(xhb + (size_t)pi.x * C_IN) + cg);
            const uint4 v01 = __ldg((const uint4*)(xhb + (size_t)pi.y * C_IN) + cg);
            const uint4 v10 = __ldg((const uint4*)(xhb + (size_t)pi.z * C_IN) + cg);
            const uint4 v11 = __ldg((const uint4*)(xhb + (size_t)pi.w * C_IN) + cg);
            uint4 hq;
            const __half2* c00 = (const __half2*)&v00;
            const __half2* c01 = (const __half2*)&v01;
            const __half2* c10 = (const __half2*)&v10;
            const __half2* c11 = (const __half2*)&v11;
            __half2* hh = (__half2*)&hq;
#pragma unroll
            for (int j = 0; j < 4; j++) {
                const float2 f00 = __half22float2(c00[j]);
                const float2 f01 = __half22float2(c01[j]);
                const float2 f10 = __half22float2(c10[j]);
                const float2 f11 = __half22float2(c11[j]);
                float2 r;
                r.x = fmaf(f00.x, pa.x, fmaf(f01.x, pa.y, fmaf(f10.x, pa.z, f11.x * pa.w)));
                r.y = fmaf(f00.y, pa.x, fmaf(f01.y, pa.y, fmaf(f10.y, pa.z, f11.y * pa.w)));
                hh[j] = __float22half2_rn(r);
            }
            *(uint4*)(A + px * ALD + cg * 8) = hq;
        }
    };

    // prologue: fill tap 0, ensure W0 resident
    fill_tap(0, 0);
    CP_WAIT0();
    __syncthreads();

    for (int k = 0; k < NTAP; k++) {
        // issue next tap's weight prefetch (overlaps with fill+GEMM below)
        const int kn = k + 1;
        if (kn < NTAP) {
            const char* src = (const char*)(g_w2 + (size_t)kn * 2 * C_IN * WLD);
            const uint32_t dst = wsm + (kn & 1) * W_TAP_B;
            for (int i = tid; i < W_TAP_B / 16; i += TPB)
                cp_async16(dst + i * 16, src + i * 16);
            CP_COMMIT();
            // fill next tap's A while this tap's GEMM runs (other-warp overlap)
            fill_tap(kn, kn & 1);
        }

        // GEMM: acc += Ah*Wh + Ah*Wl   (warp = 16 px rows)
        const __half* Wh = (const __half*)(sm + W_OFF + (k & 1) * W_TAP_B);
        const __half* Wl = Wh + C_IN * WLD;
        const __half* Ahw = (const __half*)(sm + A_OFF + (k & 1) * A_BUF_B) + wid * 16 * ALD;
#pragma unroll
        for (int kc = 0; kc < 4; kc++) {
            wmma::fragment<wmma::matrix_a, 16, 16, 16, __half, wmma::row_major> a_h;
            wmma::load_matrix_sync(a_h, Ahw + kc * 16, ALD);
#pragma unroll
            for (int n = 0; n < 4; n++) {
                wmma::fragment<wmma::matrix_b, 16, 16, 16, __half, wmma::row_major> b_h, b_l;
                wmma::load_matrix_sync(b_h, Wh + kc * 16 * WLD + n * 16, WLD);
                wmma::load_matrix_sync(b_l, Wl + kc * 16 * WLD + n * 16, WLD);
                wmma::mma_sync(acc[n], a_h, b_h, acc[n]);
                wmma::mma_sync(acc[n], a_h, b_l, acc[n]);
            }
        }

        CP_WAIT0();        // next tap's W resident (all threads, before barrier)
        __syncthreads();   // A/W buffers safe to reuse; fills visible
    }

    // epilogue: direct col-major store -> out[b][cout][px], bias already in acc
    float* ob = out + (size_t)b * C_OUT * HWO + rem + wid * 16;
#pragma unroll
    for (int n = 0; n < 4; n++)
        wmma::store_matrix_sync(ob + (size_t)(n * 16) * HWO, acc[n], HWO,
                                wmma::mem_col_major);
}

extern "C" void kernel_launch(void* const* d_in, const int* in_sizes, int n_in,
                              void* d_out, int out_size) {
    const float* x      = (const float*)d_in[0];
    const float* offset = (const float*)d_in[1];
    const float* weight = (const float*)d_in[2];
    const float* bias   = (const float*)d_in[3];
    float* out = (float*)d_out;
    (void)in_sizes; (void)n_in; (void)out_size;

    cudaFuncSetAttribute(deform_mma,
                         cudaFuncAttributeMaxDynamicSharedMemorySize, SMEM_BYTES);

    dim3 tg(HW / 32, C_IN / 32, B_N);
    transpose_h<<<tg, dim3(32, 8)>>>(x);
    prep_weights<<<(NTAP * C_IN * C_OUT + 255) / 256, 256>>>(weight);
    deform_mma<<<NPIX / TPX, TPB, SMEM_BYTES>>>(offset, bias, out);
}

// round 9
// speedup vs baseline: 3.2769x; 1.1435x over previous
#include <cuda_runtime.h>
#include <cuda_fp16.h>
#include <mma.h>
#include <cstdint>

using namespace nvcuda;

// Deformable conv2d: B=2, CIN=64, H=128, W=256, COUT=64, K=3, s=1, p=1, d=1
#define B_N   2
#define C_IN  64
#define H_IN  128
#define W_IN  256
#define C_OUT 64
#define NTAP  9
#define H_O   128
#define W_O   256
#define HW    (H_IN * W_IN)     // 32768
#define HWO   (H_O * W_O)       // 32768
#define NPIX  (B_N * HWO)       // 65536

#define TPX   128               // pixels (M) per CTA tile
#define TPB   256               // 8 warps

#define ALD   72                // A smem leading dim (fp16), mult of 8
#define WLD   72                // W smem leading dim

// dynamic smem (bytes):
//   A bufs : 2 * 128*72*2 = 36864
//   W bufs : 2 * 64*72*2  = 18432   (hi split only)
//   Pw     : float4  * 128*9 = 18432
//   Pidx   : ushort4 * 128*9 = 9216
#define A_OFF    0
#define A_BUF_B  18432
#define W_OFF    36864
#define W_TAP_B  9216
#define PW_OFF   55296
#define PI_OFF   73728
#define SMEM_BYTES 82944

__device__ __half g_xh[(size_t)B_N * HW * C_IN];   // NHWC fp16 x, 8 MB
__device__ __half g_w[NTAP * C_IN * WLD];          // [k][cin][cout+pad] fp16

__device__ __forceinline__ uint32_t smem_u32(const void* p) {
    uint32_t a;
    asm("{ .reg .u64 t; cvta.to.shared.u64 t, %1; cvt.u32.u64 %0, t; }" : "=r"(a) : "l"(p));
    return a;
}
__device__ __forceinline__ void cp_async16(uint32_t dst, const void* src) {
    asm volatile("cp.async.cg.shared.global [%0], [%1], 16;" :: "r"(dst), "l"(src));
}
#define CP_COMMIT() asm volatile("cp.async.commit_group;" ::: "memory")
#define CP_WAIT0()  asm volatile("cp.async.wait_group 0;" ::: "memory")

// ---- fused prepass: NCHW fp32 -> NHWC fp16 transpose  +  weight prep ----
// blocks [0, 1024): transpose 64hw x 64c tiles.  blocks [1024, 1033): weights.
#define T_BLOCKS (B_N * HW / 64)     // 1024
__global__ __launch_bounds__(256)
void prepass(const float* __restrict__ x, const float* __restrict__ w) {
    const int blk = blockIdx.x;
    const int t   = threadIdx.x;

    if (blk >= T_BLOCKS) {           // ---- weight prep: one tap per block ----
        const int k = blk - T_BLOCKS;
#pragma unroll
        for (int i = t; i < C_IN * C_OUT; i += 256) {
            const int cin  = i >> 6;
            const int cout = i & 63;
            g_w[(k * C_IN + cin) * WLD + cout] =
                __float2half_rn(w[(cout * C_IN + cin) * NTAP + k]);
        }
        return;
    }

    // ---- transpose tile: batch b, hw0..hw0+63, all 64 channels ----
    __shared__ float tile[64][65];
    const int b   = blk >> 9;
    const int hw0 = (blk & 511) * 64;
    const float* xb = x + (size_t)b * C_IN * HW;
    __half* xtb = g_xh + (size_t)b * HW * C_IN;

    // load: 64 c rows x 16 float4 (coalesced 256B per c-row)
    {
        const int f4 = t & 15;          // float4 index in row
        const int c0 = t >> 4;          // 16 c-rows per pass
#pragma unroll
        for (int pass = 0; pass < 4; pass++) {
            const int c = c0 + pass * 16;
            const float4 v = __ldg((const float4*)(xb + (size_t)c * HW + hw0) + f4);
            tile[c][f4 * 4 + 0] = v.x;
            tile[c][f4 * 4 + 1] = v.y;
            tile[c][f4 * 4 + 2] = v.z;
            tile[c][f4 * 4 + 3] = v.w;
        }
    }
    __syncthreads();

    // store: unit = 8 channels of one hw  (128B coalesced NHWC writes)
#pragma unroll
    for (int u = t; u < 64 * 8; u += 256) {
        const int hw = u >> 3;
        const int cg = u & 7;
        uint4 q;
        __half2* h = (__half2*)&q;
#pragma unroll
        for (int j = 0; j < 4; j++)
            h[j] = __floats2half2_rn(tile[cg * 8 + 2 * j][hw],
                                     tile[cg * 8 + 2 * j + 1][hw]);
        *(uint4*)(xtb + (size_t)(hw0 + hw) * C_IN + cg * 8) = q;
    }
}

// ---- main ----
__global__ __launch_bounds__(TPB, 2)
void deform_mma(const float* __restrict__ offset,
                const float* __restrict__ bias,
                float* __restrict__ out) {
    __shared__ float Bsm[16 * 68];
    extern __shared__ char sm[];
    float4*  Pw = (float4*)(sm + PW_OFF);     // [tap*128+px] corner weights
    ushort4* Pidx = (ushort4*)(sm + PI_OFF);  // [tap*128+px] corner indices

    const int tid = threadIdx.x;
    const int wid = tid >> 5;

    const int p0  = blockIdx.x * TPX;
    const int b   = p0 >> 15;
    const int rem = p0 & (HWO - 1);
    const int ho  = rem >> 8;
    const int wo0 = rem & (W_O - 1);

    const float* offb = offset + (size_t)b * 2 * NTAP * HWO + rem;
    const __half* xhb = g_xh + (size_t)b * HW * C_IN;
    const uint32_t wsm = smem_u32(sm + W_OFF);

    // prefetch tap-0 weights
    {
        const char* src = (const char*)(g_w);
        for (int i = tid; i < W_TAP_B / 16; i += TPB)
            cp_async16(wsm + i * 16, src + i * 16);
        CP_COMMIT();
    }
    // bias broadcast tile
    for (int i = tid; i < 16 * 64; i += TPB) {
        int r = i >> 6, c = i & 63;
        Bsm[r * 68 + c] = __ldg(bias + c);
    }

    // precompute bilinear params for ALL taps: 9*128 units
    for (int u = tid; u < NTAP * TPX; u += TPB) {
        const int k  = u >> 7;
        const int p  = u & 127;
        const float offy = __ldg(offb + (2 * k + 0) * HWO + p);
        const float offx = __ldg(offb + (2 * k + 1) * HWO + p);
        const float py = (float)(ho - 1 + k / 3) + offy;
        const float px = (float)(wo0 + p - 1 + k % 3) + offx;
        const float y0f = floorf(py);
        const float x0f = floorf(px);
        const int   y0  = (int)y0f;
        const int   x0  = (int)x0f;
        const float wy  = py - y0f;
        const float wx  = px - x0f;
        const int   y1  = y0 + 1;
        const int   x1  = x0 + 1;
        const bool vy0 = (y0 >= 0) && (y0 < H_IN);
        const bool vy1 = (y1 >= 0) && (y1 < H_IN);
        const bool vx0 = (x0 >= 0) && (x0 < W_IN);
        const bool vx1 = (x1 >= 0) && (x1 < W_IN);
        const int cy0 = min(max(y0, 0), H_IN - 1);
        const int cy1 = min(max(y1, 0), H_IN - 1);
        const int cx0 = min(max(x0, 0), W_IN - 1);
        const int cx1 = min(max(x1, 0), W_IN - 1);
        ushort4 pi;
        pi.x = (unsigned short)(cy0 * W_IN + cx0);
        pi.y = (unsigned short)(cy0 * W_IN + cx1);
        pi.z = (unsigned short)(cy1 * W_IN + cx0);
        pi.w = (unsigned short)(cy1 * W_IN + cx1);
        float4 pw;
        pw.x = (vy0 && vx0) ? (1.0f - wy) * (1.0f - wx) : 0.0f;
        pw.y = (vy0 && vx1) ? (1.0f - wy) * wx          : 0.0f;
        pw.z = (vy1 && vx0) ? wy * (1.0f - wx)          : 0.0f;
        pw.w = (vy1 && vx1) ? wy * wx                   : 0.0f;
        Pidx[u] = pi;
        Pw[u]   = pw;
    }
    __syncthreads();

    // accumulators preloaded with bias
    wmma::fragment<wmma::accumulator, 16, 16, 16, float> acc[4];
#pragma unroll
    for (int n = 0; n < 4; n++)
        wmma::load_matrix_sync(acc[n], Bsm + n * 16, 68, wmma::mem_row_major);

    // fill one tap into a given A buffer: 1024 units (px, 8-ch group)
    auto fill_tap = [&](int k, int buf) {
        __half* A = (__half*)(sm + A_OFF + buf * A_BUF_B);
#pragma unroll
        for (int i = 0; i < 4; i++) {
            const int u  = tid + TPB * i;
            const int cg = u & 7;        // channel group of 8
            const int px = u >> 3;       // pixel in tile
            const ushort4 pi = Pidx[k * TPX + px];
            const float4  pa = Pw[k * TPX + px];
            const uint4 v00 = __ldg((const uint4*)(xhb + (size_t)pi.x * C_IN) + cg);
            const uint4 v01 = __ldg((const uint4*)(xhb + (size_t)pi.y * C_IN) + cg);
            const uint4 v10 = __ldg((const uint4*)(xhb + (size_t)pi.z * C_IN) + cg);
            const uint4 v11 = __ldg((const uint4*)(xhb + (size_t)pi.w * C_IN) + cg);
            uint4 hq;
            const __half2* c00 = (const __half2*)&v00;
            const __half2* c01 = (const __half2*)&v01;
            const __half2* c10 = (const __half2*)&v10;
            const __half2* c11 = (const __half2*)&v11;
            __half2* hh = (__half2*)&hq;
#pragma unroll
            for (int j = 0; j < 4; j++) {
                const float2 f00 = __half22float2(c00[j]);
                const float2 f01 = __half22float2(c01[j]);
                const float2 f10 = __half22float2(c10[j]);
                const float2 f11 = __half22float2(c11[j]);
                float2 r;
                r.x = fmaf(f00.x, pa.x, fmaf(f01.x, pa.y, fmaf(f10.x, pa.z, f11.x * pa.w)));
                r.y = fmaf(f00.y, pa.x, fmaf(f01.y, pa.y, fmaf(f10.y, pa.z, f11.y * pa.w)));
                hh[j] = __float22half2_rn(r);
            }
            *(uint4*)(A + px * ALD + cg * 8) = hq;
        }
    };

    // prologue: fill tap 0, ensure W0 resident
    fill_tap(0, 0);
    CP_WAIT0();
    __syncthreads();

    for (int k = 0; k < NTAP; k++) {
        // issue next tap's weight prefetch + fill next tap's A (overlaps GEMM)
        const int kn = k + 1;
        if (kn < NTAP) {
            const char* src = (const char*)(g_w + (size_t)kn * C_IN * WLD);
            const uint32_t dst = wsm + (kn & 1) * W_TAP_B;
            for (int i = tid; i < W_TAP_B / 16; i += TPB)
                cp_async16(dst + i * 16, src + i * 16);
            CP_COMMIT();
            fill_tap(kn, kn & 1);
        }

        // GEMM: acc += Ah*Wh   (warp = 16 px rows)
        const __half* Wh = (const __half*)(sm + W_OFF + (k & 1) * W_TAP_B);
        const __half* Ahw = (const __half*)(sm + A_OFF + (k & 1) * A_BUF_B) + wid * 16 * ALD;
#pragma unroll
        for (int kc = 0; kc < 4; kc++) {
            wmma::fragment<wmma::matrix_a, 16, 16, 16, __half, wmma::row_major> a_h;
            wmma::load_matrix_sync(a_h, Ahw + kc * 16, ALD);
#pragma unroll
            for (int n = 0; n < 4; n++) {
                wmma::fragment<wmma::matrix_b, 16, 16, 16, __half, wmma::row_major> b_h;
                wmma::load_matrix_sync(b_h, Wh + kc * 16 * WLD + n * 16, WLD);
                wmma::mma_sync(acc[n], a_h, b_h, acc[n]);
            }
        }

        CP_WAIT0();        // next tap's W resident (all threads, before barrier)
        __syncthreads();   // A/W buffers safe to reuse; fills visible
    }

    // epilogue: direct col-major store -> out[b][cout][px], bias already in acc
    float* ob = out + (size_t)b * C_OUT * HWO + rem + wid * 16;
#pragma unroll
    for (int n = 0; n < 4; n++)
        wmma::store_matrix_sync(ob + (size_t)(n * 16) * HWO, acc[n], HWO,
                                wmma::mem_col_major);
}

extern "C" void kernel_launch(void* const* d_in, const int* in_sizes, int n_in,
                              void* d_out, int out_size) {
    const float* x      = (const float*)d_in[0];
    const float* offset = (const float*)d_in[1];
    const float* weight = (const float*)d_in[2];
    const float* bias   = (const float*)d_in[3];
    float* out = (float*)d_out;
    (void)in_sizes; (void)n_in; (void)out_size;

    cudaFuncSetAttribute(deform_mma,
                         cudaFuncAttributeMaxDynamicSharedMemorySize, SMEM_BYTES);

    prepass<<<T_BLOCKS + NTAP, 256>>>(x, weight);
    deform_mma<<<NPIX / TPX, TPB, SMEM_BYTES>>>(offset, bias, out);
}

// round 10
// speedup vs baseline: 3.3730x; 1.0293x over previous
#include <cuda_runtime.h>
#include <cuda_fp16.h>
#include <mma.h>
#include <cstdint>

using namespace nvcuda;

// Deformable conv2d: B=2, CIN=64, H=128, W=256, COUT=64, K=3, s=1, p=1, d=1
#define B_N   2
#define C_IN  64
#define H_IN  128
#define W_IN  256
#define C_OUT 64
#define NTAP  9
#define H_O   128
#define W_O   256
#define HW    (H_IN * W_IN)     // 32768
#define HWO   (H_O * W_O)       // 32768
#define NPIX  (B_N * HWO)       // 65536

#define TPX   128               // pixels (M) per CTA tile
#define TPB   256               // 8 warps

#define ALD   72                // A smem leading dim (fp16), mult of 8
#define WLD   72                // W smem leading dim

// dynamic smem (bytes), 72 KB total -> 3 CTAs/SM:
//   A bufs : 2 * 128*72*2 = 36864   (bias tile overlaid at start of buf 0)
//   W bufs : 2 * 64*72*2  = 18432
//   Pidx   : ushort4 * 128*9 = 9216
//   Pwh    : uint2   * 128*9 = 9216  (4 x fp16 corner weights)
#define A_OFF    0
#define A_BUF_B  18432
#define W_OFF    36864
#define W_TAP_B  9216
#define PI_OFF   55296
#define PWH_OFF  64512
#define SMEM_BYTES 73728

__device__ __half g_xh[(size_t)B_N * HW * C_IN];   // NHWC fp16 x, 8 MB
__device__ __half g_w[NTAP * C_IN * WLD];          // [k][cin][cout+pad] fp16

__device__ __forceinline__ uint32_t smem_u32(const void* p) {
    uint32_t a;
    asm("{ .reg .u64 t; cvta.to.shared.u64 t, %1; cvt.u32.u64 %0, t; }" : "=r"(a) : "l"(p));
    return a;
}
__device__ __forceinline__ void cp_async16(uint32_t dst, const void* src) {
    asm volatile("cp.async.cg.shared.global [%0], [%1], 16;" :: "r"(dst), "l"(src));
}
#define CP_COMMIT() asm volatile("cp.async.commit_group;" ::: "memory")
#define CP_WAIT0()  asm volatile("cp.async.wait_group 0;" ::: "memory")

// ---- fused prepass: NCHW fp32 -> NHWC fp16 transpose  +  weight prep ----
#define T_BLOCKS (B_N * HW / 64)     // 1024
__global__ __launch_bounds__(256)
void prepass(const float* __restrict__ x, const float* __restrict__ w) {
    const int blk = blockIdx.x;
    const int t   = threadIdx.x;

    if (blk >= T_BLOCKS) {           // ---- weight prep: one tap per block ----
        const int k = blk - T_BLOCKS;
#pragma unroll
        for (int i = t; i < C_IN * C_OUT; i += 256) {
            const int cin  = i >> 6;
            const int cout = i & 63;
            g_w[(k * C_IN + cin) * WLD + cout] =
                __float2half_rn(w[(cout * C_IN + cin) * NTAP + k]);
        }
        return;
    }

    // ---- transpose tile: batch b, hw0..hw0+63, all 64 channels ----
    __shared__ float tile[64][65];
    const int b   = blk >> 9;
    const int hw0 = (blk & 511) * 64;
    const float* xb = x + (size_t)b * C_IN * HW;
    __half* xtb = g_xh + (size_t)b * HW * C_IN;

    {
        const int f4 = t & 15;
        const int c0 = t >> 4;
#pragma unroll
        for (int pass = 0; pass < 4; pass++) {
            const int c = c0 + pass * 16;
            const float4 v = __ldg((const float4*)(xb + (size_t)c * HW + hw0) + f4);
            tile[c][f4 * 4 + 0] = v.x;
            tile[c][f4 * 4 + 1] = v.y;
            tile[c][f4 * 4 + 2] = v.z;
            tile[c][f4 * 4 + 3] = v.w;
        }
    }
    __syncthreads();

#pragma unroll
    for (int u = t; u < 64 * 8; u += 256) {
        const int hw = u >> 3;
        const int cg = u & 7;
        uint4 q;
        __half2* h = (__half2*)&q;
#pragma unroll
        for (int j = 0; j < 4; j++)
            h[j] = __floats2half2_rn(tile[cg * 8 + 2 * j][hw],
                                     tile[cg * 8 + 2 * j + 1][hw]);
        *(uint4*)(xtb + (size_t)(hw0 + hw) * C_IN + cg * 8) = q;
    }
}

// ---- main ----
__global__ __launch_bounds__(TPB, 3)
void deform_mma(const float* __restrict__ offset,
                const float* __restrict__ bias,
                float* __restrict__ out) {
    extern __shared__ char sm[];
    ushort4* Pidx = (ushort4*)(sm + PI_OFF);   // [tap*128+px] corner indices
    uint2*   Pwh  = (uint2*)(sm + PWH_OFF);    // [tap*128+px] 4 x fp16 weights
    float*   Bsm  = (float*)(sm + A_OFF);      // bias tile, overlaid in A buf 0

    const int tid = threadIdx.x;
    const int wid = tid >> 5;

    const int p0  = blockIdx.x * TPX;
    const int b   = p0 >> 15;
    const int rem = p0 & (HWO - 1);
    const int ho  = rem >> 8;
    const int wo0 = rem & (W_O - 1);

    const float* offb = offset + (size_t)b * 2 * NTAP * HWO + rem;
    const __half* xhb = g_xh + (size_t)b * HW * C_IN;
    const uint32_t wsm = smem_u32(sm + W_OFF);

    // prefetch tap-0 weights
    {
        const char* src = (const char*)(g_w);
        for (int i = tid; i < W_TAP_B / 16; i += TPB)
            cp_async16(wsm + i * 16, src + i * 16);
        CP_COMMIT();
    }
    // bias broadcast tile (in A buf 0, consumed before first fill)
    for (int i = tid; i < 16 * 64; i += TPB) {
        int r = i >> 6, c = i & 63;
        Bsm[r * 68 + c] = __ldg(bias + c);
    }

    // precompute bilinear params for ALL taps: 9*128 units
    for (int u = tid; u < NTAP * TPX; u += TPB) {
        const int k  = u >> 7;
        const int p  = u & 127;
        const float offy = __ldg(offb + (2 * k + 0) * HWO + p);
        const float offx = __ldg(offb + (2 * k + 1) * HWO + p);
        const float py = (float)(ho - 1 + k / 3) + offy;
        const float px = (float)(wo0 + p - 1 + k % 3) + offx;
        const float y0f = floorf(py);
        const float x0f = floorf(px);
        const int   y0  = (int)y0f;
        const int   x0  = (int)x0f;
        const float wy  = py - y0f;
        const float wx  = px - x0f;
        const int   y1  = y0 + 1;
        const int   x1  = x0 + 1;
        const bool vy0 = (y0 >= 0) && (y0 < H_IN);
        const bool vy1 = (y1 >= 0) && (y1 < H_IN);
        const bool vx0 = (x0 >= 0) && (x0 < W_IN);
        const bool vx1 = (x1 >= 0) && (x1 < W_IN);
        const int cy0 = min(max(y0, 0), H_IN - 1);
        const int cy1 = min(max(y1, 0), H_IN - 1);
        const int cx0 = min(max(x0, 0), W_IN - 1);
        const int cx1 = min(max(x1, 0), W_IN - 1);
        ushort4 pi;
        pi.x = (unsigned short)(cy0 * W_IN + cx0);
        pi.y = (unsigned short)(cy0 * W_IN + cx1);
        pi.z = (unsigned short)(cy1 * W_IN + cx0);
        pi.w = (unsigned short)(cy1 * W_IN + cx1);
        const float w00 = (vy0 && vx0) ? (1.0f - wy) * (1.0f - wx) : 0.0f;
        const float w01 = (vy0 && vx1) ? (1.0f - wy) * wx          : 0.0f;
        const float w10 = (vy1 && vx0) ? wy * (1.0f - wx)          : 0.0f;
        const float w11 = (vy1 && vx1) ? wy * wx                   : 0.0f;
        uint2 pw;
        const __half2 h01 = __floats2half2_rn(w00, w01);
        const __half2 h23 = __floats2half2_rn(w10, w11);
        pw.x = *(const uint32_t*)&h01;
        pw.y = *(const uint32_t*)&h23;
        Pidx[u] = pi;
        Pwh[u]  = pw;
    }
    __syncthreads();

    // accumulators preloaded with bias
    wmma::fragment<wmma::accumulator, 16, 16, 16, float> acc[4];
#pragma unroll
    for (int n = 0; n < 4; n++)
        wmma::load_matrix_sync(acc[n], Bsm + n * 16, 68, wmma::mem_row_major);
    __syncthreads();   // all warps done reading Bsm before fill overwrites it

    // fill one tap into a given A buffer: 1024 units (px, 8-ch group)
    auto fill_tap = [&](int k, int buf) {
        __half* A = (__half*)(sm + A_OFF + buf * A_BUF_B);
#pragma unroll
        for (int i = 0; i < 4; i++) {
            const int u  = tid + TPB * i;
            const int cg = u & 7;        // channel group of 8
            const int px = u >> 3;       // pixel in tile
            const ushort4 pi = Pidx[k * TPX + px];
            const uint2   pw = Pwh[k * TPX + px];
            const float2 w01 = __half22float2(*(const __half2*)&pw.x);
            const float2 w23 = __half22float2(*(const __half2*)&pw.y);
            const uint4 v00 = __ldg((const uint4*)(xhb + (size_t)pi.x * C_IN) + cg);
            const uint4 v01 = __ldg((const uint4*)(xhb + (size_t)pi.y * C_IN) + cg);
            const uint4 v10 = __ldg((const uint4*)(xhb + (size_t)pi.z * C_IN) + cg);
            const uint4 v11 = __ldg((const uint4*)(xhb + (size_t)pi.w * C_IN) + cg);
            uint4 hq;
            const __half2* c00 = (const __half2*)&v00;
            const __half2* c01 = (const __half2*)&v01;
            const __half2* c10 = (const __half2*)&v10;
            const __half2* c11 = (const __half2*)&v11;
            __half2* hh = (__half2*)&hq;
#pragma unroll
            for (int j = 0; j < 4; j++) {
                const float2 f00 = __half22float2(c00[j]);
                const float2 f01 = __half22float2(c01[j]);
                const float2 f10 = __half22float2(c10[j]);
                const float2 f11 = __half22float2(c11[j]);
                float2 r;
                r.x = fmaf(f00.x, w01.x, fmaf(f01.x, w01.y, fmaf(f10.x, w23.x, f11.x * w23.y)));
                r.y = fmaf(f00.y, w01.x, fmaf(f01.y, w01.y, fmaf(f10.y, w23.x, f11.y * w23.y)));
                hh[j] = __float22half2_rn(r);
            }
            *(uint4*)(A + px * ALD + cg * 8) = hq;
        }
    };

    // prologue: fill tap 0, ensure W0 resident
    fill_tap(0, 0);
    CP_WAIT0();
    __syncthreads();

    for (int k = 0; k < NTAP; k++) {
        // issue next tap's weight prefetch + fill next tap's A (overlaps GEMM)
        const int kn = k + 1;
        if (kn < NTAP) {
            const char* src = (const char*)(g_w + (size_t)kn * C_IN * WLD);
            const uint32_t dst = wsm + (kn & 1) * W_TAP_B;
            for (int i = tid; i < W_TAP_B / 16; i += TPB)
                cp_async16(dst + i * 16, src + i * 16);
            CP_COMMIT();
            fill_tap(kn, kn & 1);
        }

        // GEMM: acc += Ah*Wh   (warp = 16 px rows)
        const __half* Wh = (const __half*)(sm + W_OFF + (k & 1) * W_TAP_B);
        const __half* Ahw = (const __half*)(sm + A_OFF + (k & 1) * A_BUF_B) + wid * 16 * ALD;
#pragma unroll
        for (int kc = 0; kc < 4; kc++) {
            wmma::fragment<wmma::matrix_a, 16, 16, 16, __half, wmma::row_major> a_h;
            wmma::load_matrix_sync(a_h, Ahw + kc * 16, ALD);
#pragma unroll
            for (int n = 0; n < 4; n++) {
                wmma::fragment<wmma::matrix_b, 16, 16, 16, __half, wmma::row_major> b_h;
                wmma::load_matrix_sync(b_h, Wh + kc * 16 * WLD + n * 16, WLD);
                wmma::mma_sync(acc[n], a_h, b_h, acc[n]);
            }
        }

        CP_WAIT0();        // next tap's W resident (all threads, before barrier)
        __syncthreads();   // A/W buffers safe to reuse; fills visible
    }

    // epilogue: direct col-major store -> out[b][cout][px], bias already in acc
    float* ob = out + (size_t)b * C_OUT * HWO + rem + wid * 16;
#pragma unroll
    for (int n = 0; n < 4; n++)
        wmma::store_matrix_sync(ob + (size_t)(n * 16) * HWO, acc[n], HWO,
                                wmma::mem_col_major);
}

extern "C" void kernel_launch(void* const* d_in, const int* in_sizes, int n_in,
                              void* d_out, int out_size) {
    const float* x      = (const float*)d_in[0];
    const float* offset = (const float*)d_in[1];
    const float* weight = (const float*)d_in[2];
    const float* bias   = (const float*)d_in[3];
    float* out = (float*)d_out;
    (void)in_sizes; (void)n_in; (void)out_size;

    cudaFuncSetAttribute(deform_mma,
                         cudaFuncAttributeMaxDynamicSharedMemorySize, SMEM_BYTES);

    prepass<<<T_BLOCKS + NTAP, 256>>>(x, weight);
    deform_mma<<<NPIX / TPX, TPB, SMEM_BYTES>>>(offset, bias, out);
}